// round 3
// baseline (speedup 1.0000x reference)
#include <cuda_runtime.h>
#include <math.h>

#define T_LEN   8192
#define F_DIM   8
#define B_SZ    128
#define NLAGS   24
#define THREADS 512
#define NWARPS  (THREADS / 32)      // 16
#define CHUNK   (T_LEN / THREADS)   // 16
#define WIN     (CHUNK + NLAGS)     // 40-element register window

__device__ float g_partials[B_SZ];
__device__ int   g_count = 0;

// padded smem index: kills bank conflicts on stride-16 window loads
__device__ __forceinline__ int zi(int t) { return t + (t >> 5); }

__global__ __launch_bounds__(THREADS)
void autocorr_kernel(const float* __restrict__ input,
                     const float* __restrict__ lagw,
                     const float* __restrict__ seas,
                     float* __restrict__ out) {
    __shared__ float zs[T_LEN + (T_LEN >> 5)];
    __shared__ float red[2 * NWARPS];
    __shared__ float warp_sxy[NWARPS][NLAGS];

    const int b    = blockIdx.x;
    const int tid  = threadIdx.x;
    const int warp = tid >> 5;
    const int lane = tid & 31;
    const float* row = input + (size_t)b * T_LEN * F_DIM;

    // ---- load stride-8 column -> smem; raw sum / sumsq on the fly ----
    float lsum = 0.f, lsq = 0.f;
    #pragma unroll
    for (int k = 0; k < CHUNK; k++) {
        int t = tid + k * THREADS;
        float v = __ldg(row + (size_t)t * F_DIM);
        zs[zi(t)] = v;
        lsum += v;
        lsq  += v * v;
    }
    #pragma unroll
    for (int o = 16; o > 0; o >>= 1) {
        lsum += __shfl_xor_sync(0xffffffffu, lsum, o);
        lsq  += __shfl_xor_sync(0xffffffffu, lsq,  o);
    }
    if (lane == 0) { red[warp] = lsum; red[NWARPS + warp] = lsq; }

    __syncthreads();   // full row + red visible

    // ---- cross-products from a 40-elem register window (raw data:
    //      Pearson per window is invariant to the global normalization) ----
    float w[WIN];
    const int i0 = tid * CHUNK;
    #pragma unroll
    for (int j = 0; j < WIN; j++) {
        int idx = i0 + j;
        w[j] = (idx < T_LEN) ? zs[zi(idx)] : 0.f;   // zero-pad kills invalid products
    }
    float acc[NLAGS];
    #pragma unroll
    for (int l = 0; l < NLAGS; l++) acc[l] = 0.f;
    #pragma unroll
    for (int j = 0; j < CHUNK; j++) {
        #pragma unroll
        for (int l = 0; l < NLAGS; l++)
            acc[l] = fmaf(w[j], w[j + l + 1], acc[l]);
    }

    // ---- per-lag reduction: warp shuffle -> smem ----
    #pragma unroll
    for (int l = 0; l < NLAGS; l++) {
        float v = acc[l];
        #pragma unroll
        for (int o = 16; o > 0; o >>= 1)
            v += __shfl_xor_sync(0xffffffffu, v, o);
        if (lane == 0) warp_sxy[warp][l] = v;
    }
    __syncthreads();

    // ---- epilogue: one warp finishes the whole row ----
    if (warp == 0) {
        // softmax(lag_weights) across lanes 0..23 (+ seasonal adds)
        float e = (lane < NLAGS) ? __expf(__ldg(lagw + lane)) : 0.f;
        float se = e;
        #pragma unroll
        for (int o = 16; o > 0; o >>= 1) se += __shfl_xor_sync(0xffffffffu, se, o);
        float coef = e / se;
        if (lane == 11) coef += __ldg(seas + 0);   // lag 12
        if (lane == 23) coef += __ldg(seas + 1);   // lag 24

        float val = 0.f;
        if (lane < NLAGS) {
            const int l   = lane;
            const int lag = l + 1;
            float sxy = 0.f;
            #pragma unroll
            for (int wi = 0; wi < NWARPS; wi++) sxy += warp_sxy[wi][l];

            float S = 0.f, Q = 0.f;
            #pragma unroll
            for (int i = 0; i < NWARPS; i++) { S += red[i]; Q += red[NWARPS + i]; }

            // head/tail partial sums (<=24 elements each)
            float hs = 0.f, hq = 0.f, ts = 0.f, tq = 0.f;
            for (int t = 0; t < lag; t++)            { float v = zs[zi(t)]; hs += v; hq += v * v; }
            for (int t = T_LEN - lag; t < T_LEN; t++){ float v = zs[zi(t)]; ts += v; tq += v * v; }

            const float Sx  = S - ts,  Sy  = S - hs;
            const float Sxx = Q - tq,  Syy = Q - hq;
            const float n   = (float)(T_LEN - lag);

            float num = sxy - Sx * Sy / n;
            float vx  = Sxx - Sx * Sx / n;
            float vy  = Syy - Sy * Sy / n;
            float r   = num / (sqrtf(fmaxf(vx, 0.f)) * sqrtf(fmaxf(vy, 0.f)));
            r = fminf(1.f, fmaxf(-1.f, r));
            val = r * coef;
        }
        #pragma unroll
        for (int o = 16; o > 0; o >>= 1) val += __shfl_xor_sync(0xffffffffu, val, o);

        int ticket = 0;
        if (lane == 0) {
            g_partials[b] = val;
            __threadfence();
            ticket = atomicAdd(&g_count, 1);
        }
        ticket = __shfl_sync(0xffffffffu, ticket, 0);

        if (ticket == B_SZ - 1) {   // last block folds the 128 row partials
            __threadfence();
            float s = g_partials[lane] + g_partials[lane + 32]
                    + g_partials[lane + 64] + g_partials[lane + 96];
            #pragma unroll
            for (int o = 16; o > 0; o >>= 1) s += __shfl_xor_sync(0xffffffffu, s, o);
            if (lane == 0) {
                out[0] = s * (1.f / (float)B_SZ);
                g_count = 0;   // reset for next graph replay
            }
        }
    }
}

extern "C" void kernel_launch(void* const* d_in, const int* in_sizes, int n_in,
                              void* d_out, int out_size) {
    const float* input = (const float*)d_in[0];   // input_sequence (128,8192,8)
    // d_in[1] = hidden_states — never referenced by the math; intentionally unused
    const float* lagw  = (const float*)d_in[2];   // lag_weights (24,)
    const float* seas  = (const float*)d_in[3];   // seasonal_importance (2,)
    float* out = (float*)d_out;

    autocorr_kernel<<<B_SZ, THREADS>>>(input, lagw, seas, out);
}

// round 4
// speedup vs baseline: 1.0025x; 1.0025x over previous
#include <cuda_runtime.h>
#include <math.h>

#define T_LEN   8192
#define F_DIM   8
#define B_SZ    128
#define NLAGS   24
#define THREADS 256
#define NWARPS  (THREADS / 32)      // 8
#define CHUNK   (T_LEN / THREADS)   // 32 -> 32-deep front-batched load burst
#define WIN     (CHUNK + NLAGS)     // 56-element register window

__device__ float g_partials[B_SZ];
__device__ int   g_count = 0;

// padded smem index: kills bank conflicts on stride-32 window loads
__device__ __forceinline__ int zi(int t) { return t + (t >> 5); }

__global__ __launch_bounds__(THREADS)
void autocorr_kernel(const float* __restrict__ input,
                     const float* __restrict__ lagw,
                     const float* __restrict__ seas,
                     float* __restrict__ out) {
    __shared__ float zs[T_LEN + (T_LEN >> 5)];
    __shared__ float red[2 * NWARPS];
    __shared__ float warp_sxy[NWARPS][NLAGS];

    const int b    = blockIdx.x;
    const int tid  = threadIdx.x;
    const int warp = tid >> 5;
    const int lane = tid & 31;
    const float* row = input + (size_t)b * T_LEN * F_DIM;

    // ---- single fully-unrolled 32-deep load burst (max MLP), sums on the fly ----
    float lsum = 0.f, lsq = 0.f;
    #pragma unroll
    for (int k = 0; k < CHUNK; k++) {
        int t = tid + k * THREADS;
        float v = __ldg(row + (size_t)t * F_DIM);
        zs[zi(t)] = v;
        lsum += v;
        lsq  += v * v;
    }
    #pragma unroll
    for (int o = 16; o > 0; o >>= 1) {
        lsum += __shfl_xor_sync(0xffffffffu, lsum, o);
        lsq  += __shfl_xor_sync(0xffffffffu, lsq,  o);
    }
    if (lane == 0) { red[warp] = lsum; red[NWARPS + warp] = lsq; }

    __syncthreads();   // full row + red visible

    // ---- cross-products from a 56-elem register window (raw data:
    //      Pearson per window is invariant to the global normalization) ----
    float w[WIN];
    const int i0 = tid * CHUNK;
    #pragma unroll
    for (int j = 0; j < WIN; j++) {
        int idx = i0 + j;
        w[j] = (idx < T_LEN) ? zs[zi(idx)] : 0.f;   // zero-pad kills invalid products
    }
    float acc[NLAGS];
    #pragma unroll
    for (int l = 0; l < NLAGS; l++) acc[l] = 0.f;
    #pragma unroll
    for (int j = 0; j < CHUNK; j++) {
        #pragma unroll
        for (int l = 0; l < NLAGS; l++)
            acc[l] = fmaf(w[j], w[j + l + 1], acc[l]);
    }

    // ---- per-lag reduction: warp shuffle -> smem ----
    #pragma unroll
    for (int l = 0; l < NLAGS; l++) {
        float v = acc[l];
        #pragma unroll
        for (int o = 16; o > 0; o >>= 1)
            v += __shfl_xor_sync(0xffffffffu, v, o);
        if (lane == 0) warp_sxy[warp][l] = v;
    }
    __syncthreads();

    // ---- epilogue: one warp finishes the whole row ----
    if (warp == 0) {
        // softmax(lag_weights) across lanes 0..23 (+ seasonal adds)
        float e = (lane < NLAGS) ? __expf(__ldg(lagw + lane)) : 0.f;
        float se = e;
        #pragma unroll
        for (int o = 16; o > 0; o >>= 1) se += __shfl_xor_sync(0xffffffffu, se, o);
        float coef = e / se;
        if (lane == 11) coef += __ldg(seas + 0);   // lag 12
        if (lane == 23) coef += __ldg(seas + 1);   // lag 24

        float val = 0.f;
        if (lane < NLAGS) {
            const int l   = lane;
            const int lag = l + 1;
            float sxy = 0.f;
            #pragma unroll
            for (int wi = 0; wi < NWARPS; wi++) sxy += warp_sxy[wi][l];

            float S = 0.f, Q = 0.f;
            #pragma unroll
            for (int i = 0; i < NWARPS; i++) { S += red[i]; Q += red[NWARPS + i]; }

            // head/tail partial sums (<=24 elements each)
            float hs = 0.f, hq = 0.f, ts = 0.f, tq = 0.f;
            for (int t = 0; t < lag; t++)            { float v = zs[zi(t)]; hs += v; hq += v * v; }
            for (int t = T_LEN - lag; t < T_LEN; t++){ float v = zs[zi(t)]; ts += v; tq += v * v; }

            const float Sx  = S - ts,  Sy  = S - hs;
            const float Sxx = Q - tq,  Syy = Q - hq;
            const float n   = (float)(T_LEN - lag);

            float num = sxy - Sx * Sy / n;
            float vx  = Sxx - Sx * Sx / n;
            float vy  = Syy - Sy * Sy / n;
            float r   = num / (sqrtf(fmaxf(vx, 0.f)) * sqrtf(fmaxf(vy, 0.f)));
            r = fminf(1.f, fmaxf(-1.f, r));
            val = r * coef;
        }
        #pragma unroll
        for (int o = 16; o > 0; o >>= 1) val += __shfl_xor_sync(0xffffffffu, val, o);

        int ticket = 0;
        if (lane == 0) {
            g_partials[b] = val;
            __threadfence();
            ticket = atomicAdd(&g_count, 1);
        }
        ticket = __shfl_sync(0xffffffffu, ticket, 0);

        if (ticket == B_SZ - 1) {   // last block folds the 128 row partials
            __threadfence();
            float s = g_partials[lane] + g_partials[lane + 32]
                    + g_partials[lane + 64] + g_partials[lane + 96];
            #pragma unroll
            for (int o = 16; o > 0; o >>= 1) s += __shfl_xor_sync(0xffffffffu, s, o);
            if (lane == 0) {
                out[0] = s * (1.f / (float)B_SZ);
                g_count = 0;   // reset for next graph replay
            }
        }
    }
}

extern "C" void kernel_launch(void* const* d_in, const int* in_sizes, int n_in,
                              void* d_out, int out_size) {
    const float* input = (const float*)d_in[0];   // input_sequence (128,8192,8)
    // d_in[1] = hidden_states — never referenced by the math; intentionally unused
    const float* lagw  = (const float*)d_in[2];   // lag_weights (24,)
    const float* seas  = (const float*)d_in[3];   // seasonal_importance (2,)
    float* out = (float*)d_out;

    autocorr_kernel<<<B_SZ, THREADS>>>(input, lagw, seas, out);
}

// round 5
// speedup vs baseline: 1.0226x; 1.0201x over previous
#include <cuda_runtime.h>
#include <math.h>

#define T_LEN   8192
#define F_DIM   8
#define B_SZ    128
#define NLAGS   24
#define THREADS 256
#define NWARPS  (THREADS / 32)      // 8
#define CHUNK   (T_LEN / THREADS)   // 32 elements per thread
#define HBATCH  16                  // float4 staging batch (64 regs)
#define WIN     (CHUNK + NLAGS)     // 56-element register window

__device__ float g_partials[B_SZ];
__device__ int   g_count = 0;

// padded smem index: kills bank conflicts on stride-32 window loads
__device__ __forceinline__ int zi(int t) { return t + (t >> 5); }

__global__ __launch_bounds__(THREADS)
void autocorr_kernel(const float* __restrict__ input,
                     const float* __restrict__ lagw,
                     const float* __restrict__ seas,
                     float* __restrict__ out) {
    __shared__ float zs[T_LEN + (T_LEN >> 5)];
    __shared__ float red[2 * NWARPS];
    __shared__ float warp_sxy[NWARPS][NLAGS];

    const int b    = blockIdx.x;
    const int tid  = threadIdx.x;
    const int warp = tid >> 5;
    const int lane = tid & 31;
    // element t's features live at bytes [32t, 32t+32); f0..f3 = float4 index 2t
    const float4* row4 = (const float4*)(input + (size_t)b * T_LEN * F_DIM);

    // ---- load via float4 (4x bytes per L1 wavefront vs scalar gather) ----
    float lsum = 0.f, lsq = 0.f;
    float4 st[HBATCH];

    #pragma unroll
    for (int k = 0; k < HBATCH; k++) {
        int t = tid + k * THREADS;
        st[k] = __ldg(row4 + 2 * (size_t)t);
    }
    #pragma unroll
    for (int k = 0; k < HBATCH; k++) {
        int t = tid + k * THREADS;
        float v = st[k].x;
        zs[zi(t)] = v;
        lsum += v;
        lsq  += v * v;
    }
    #pragma unroll
    for (int k = 0; k < HBATCH; k++) {
        int t = tid + (k + HBATCH) * THREADS;
        st[k] = __ldg(row4 + 2 * (size_t)t);
    }
    #pragma unroll
    for (int k = 0; k < HBATCH; k++) {
        int t = tid + (k + HBATCH) * THREADS;
        float v = st[k].x;
        zs[zi(t)] = v;
        lsum += v;
        lsq  += v * v;
    }

    #pragma unroll
    for (int o = 16; o > 0; o >>= 1) {
        lsum += __shfl_xor_sync(0xffffffffu, lsum, o);
        lsq  += __shfl_xor_sync(0xffffffffu, lsq,  o);
    }
    if (lane == 0) { red[warp] = lsum; red[NWARPS + warp] = lsq; }

    __syncthreads();   // full row + red visible

    // ---- cross-products from a 56-elem register window (raw data:
    //      Pearson per window is invariant to the global normalization) ----
    float w[WIN];
    const int i0 = tid * CHUNK;
    #pragma unroll
    for (int j = 0; j < WIN; j++) {
        int idx = i0 + j;
        w[j] = (idx < T_LEN) ? zs[zi(idx)] : 0.f;   // zero-pad kills invalid products
    }
    float acc[NLAGS];
    #pragma unroll
    for (int l = 0; l < NLAGS; l++) acc[l] = 0.f;
    #pragma unroll
    for (int j = 0; j < CHUNK; j++) {
        #pragma unroll
        for (int l = 0; l < NLAGS; l++)
            acc[l] = fmaf(w[j], w[j + l + 1], acc[l]);
    }

    // ---- per-lag reduction: warp shuffle -> smem ----
    #pragma unroll
    for (int l = 0; l < NLAGS; l++) {
        float v = acc[l];
        #pragma unroll
        for (int o = 16; o > 0; o >>= 1)
            v += __shfl_xor_sync(0xffffffffu, v, o);
        if (lane == 0) warp_sxy[warp][l] = v;
    }
    __syncthreads();

    // ---- epilogue: one warp finishes the whole row ----
    if (warp == 0) {
        // softmax(lag_weights) across lanes 0..23 (+ seasonal adds)
        float e = (lane < NLAGS) ? __expf(__ldg(lagw + lane)) : 0.f;
        float se = e;
        #pragma unroll
        for (int o = 16; o > 0; o >>= 1) se += __shfl_xor_sync(0xffffffffu, se, o);
        float coef = e / se;
        if (lane == 11) coef += __ldg(seas + 0);   // lag 12
        if (lane == 23) coef += __ldg(seas + 1);   // lag 24

        float val = 0.f;
        if (lane < NLAGS) {
            const int l   = lane;
            const int lag = l + 1;
            float sxy = 0.f;
            #pragma unroll
            for (int wi = 0; wi < NWARPS; wi++) sxy += warp_sxy[wi][l];

            float S = 0.f, Q = 0.f;
            #pragma unroll
            for (int i = 0; i < NWARPS; i++) { S += red[i]; Q += red[NWARPS + i]; }

            // head/tail partial sums (<=24 elements each)
            float hs = 0.f, hq = 0.f, ts = 0.f, tq = 0.f;
            for (int t = 0; t < lag; t++)            { float v = zs[zi(t)]; hs += v; hq += v * v; }
            for (int t = T_LEN - lag; t < T_LEN; t++){ float v = zs[zi(t)]; ts += v; tq += v * v; }

            const float Sx  = S - ts,  Sy  = S - hs;
            const float Sxx = Q - tq,  Syy = Q - hq;
            const float n   = (float)(T_LEN - lag);

            float num = sxy - Sx * Sy / n;
            float vx  = Sxx - Sx * Sx / n;
            float vy  = Syy - Sy * Sy / n;
            float r   = num / (sqrtf(fmaxf(vx, 0.f)) * sqrtf(fmaxf(vy, 0.f)));
            r = fminf(1.f, fmaxf(-1.f, r));
            val = r * coef;
        }
        #pragma unroll
        for (int o = 16; o > 0; o >>= 1) val += __shfl_xor_sync(0xffffffffu, val, o);

        int ticket = 0;
        if (lane == 0) {
            g_partials[b] = val;
            __threadfence();
            ticket = atomicAdd(&g_count, 1);
        }
        ticket = __shfl_sync(0xffffffffu, ticket, 0);

        if (ticket == B_SZ - 1) {   // last block folds the 128 row partials
            __threadfence();
            float s = g_partials[lane] + g_partials[lane + 32]
                    + g_partials[lane + 64] + g_partials[lane + 96];
            #pragma unroll
            for (int o = 16; o > 0; o >>= 1) s += __shfl_xor_sync(0xffffffffu, s, o);
            if (lane == 0) {
                out[0] = s * (1.f / (float)B_SZ);
                g_count = 0;   // reset for next graph replay
            }
        }
    }
}

extern "C" void kernel_launch(void* const* d_in, const int* in_sizes, int n_in,
                              void* d_out, int out_size) {
    const float* input = (const float*)d_in[0];   // input_sequence (128,8192,8)
    // d_in[1] = hidden_states — never referenced by the math; intentionally unused
    const float* lagw  = (const float*)d_in[2];   // lag_weights (24,)
    const float* seas  = (const float*)d_in[3];   // seasonal_importance (2,)
    float* out = (float*)d_out;

    autocorr_kernel<<<B_SZ, THREADS>>>(input, lagw, seas, out);
}